// round 15
// baseline (speedup 1.0000x reference)
#include <cuda_runtime.h>
#include <cuda_bf16.h>
#include <cuda_fp16.h>
#include <cstdint>

#define BS 16
#define SEQ 1024
#define DM 256
#define NH 8
#define QKDIM (NH*DM)   // 2048

typedef unsigned long long u64;

// ---------------- mma.sync / ldmatrix / cp.async helpers ----------------
__device__ __forceinline__ uint32_t smem_u32(const void* p) {
    uint32_t a;
    asm("{ .reg .u64 t; cvta.to.shared.u64 t, %1; cvt.u32.u64 %0, t; }" : "=r"(a) : "l"(p));
    return a;
}
__device__ __forceinline__ void ldsm4(uint32_t* r, uint32_t addr) {
    asm volatile("ldmatrix.sync.aligned.m8n8.x4.shared.b16 {%0,%1,%2,%3}, [%4];"
        : "=r"(r[0]), "=r"(r[1]), "=r"(r[2]), "=r"(r[3]) : "r"(addr));
}
__device__ __forceinline__ void ldsm4t(uint32_t* r, uint32_t addr) {
    asm volatile("ldmatrix.sync.aligned.m8n8.x4.trans.shared.b16 {%0,%1,%2,%3}, [%4];"
        : "=r"(r[0]), "=r"(r[1]), "=r"(r[2]), "=r"(r[3]) : "r"(addr));
}
__device__ __forceinline__ void mma_bf16(float* c, const uint32_t* a, uint32_t b0, uint32_t b1) {
    asm volatile("mma.sync.aligned.m16n8k16.row.col.f32.bf16.bf16.f32 "
        "{%0,%1,%2,%3}, {%4,%5,%6,%7}, {%8,%9}, {%0,%1,%2,%3};"
        : "+f"(c[0]), "+f"(c[1]), "+f"(c[2]), "+f"(c[3])
        : "r"(a[0]), "r"(a[1]), "r"(a[2]), "r"(a[3]), "r"(b0), "r"(b1));
}
__device__ __forceinline__ void mma_fp16(float* c, const uint32_t* a, uint32_t b0, uint32_t b1) {
    asm volatile("mma.sync.aligned.m16n8k16.row.col.f32.f16.f16.f32 "
        "{%0,%1,%2,%3}, {%4,%5,%6,%7}, {%8,%9}, {%0,%1,%2,%3};"
        : "+f"(c[0]), "+f"(c[1]), "+f"(c[2]), "+f"(c[3])
        : "r"(a[0]), "r"(a[1]), "r"(a[2]), "r"(a[3]), "r"(b0), "r"(b1));
}
__device__ __forceinline__ void cpa16(uint32_t saddr, const void* g) {
    asm volatile("cp.async.cg.shared.global [%0], [%1], 16;" :: "r"(saddr), "l"(g));
}
#define CP_COMMIT() asm volatile("cp.async.commit_group;" ::: "memory")
#define CP_WAIT(n)  asm volatile("cp.async.wait_group %0;" :: "n"(n) : "memory")

__device__ __forceinline__ uint32_t pack_bf16x2(float a, float b) {
    __nv_bfloat162 h = __floats2bfloat162_rn(a, b);
    return *reinterpret_cast<uint32_t*>(&h);
}
__device__ __forceinline__ uint32_t pack_h2(float a, float b) {
    __half2 h = __floats2half2_rn(a, b);
    return *reinterpret_cast<uint32_t*>(&h);
}
__device__ __forceinline__ void split2(float a, float b, uint32_t& hi, uint32_t& lo) {
    __nv_bfloat16 ha = __float2bfloat16_rn(a), hb = __float2bfloat16_rn(b);
    __nv_bfloat162 H; H.x = ha; H.y = hb;
    hi = *reinterpret_cast<uint32_t*>(&H);
    lo = pack_bf16x2(a - __bfloat162float(ha), b - __bfloat162float(hb));
}
__device__ __forceinline__ void split2h(float a, float b, uint32_t& hi, uint32_t& lo) {
    __half ha = __float2half_rn(a), hb = __float2half_rn(b);
    __half2 H; H.x = ha; H.y = hb;
    hi = *reinterpret_cast<uint32_t*>(&H);
    lo = pack_h2(a - __half2float(ha), b - __half2float(hb));
}

// ---------------- scratch ----------------
__device__ float g_xn[BS*SEQ*DM];
__device__ __half g_qh [BS*SEQ*QKDIM];
__device__ __half g_khi[BS*SEQ*QKDIM];
__device__ __half g_klo[BS*SEQ*QKDIM];
__device__ float g_ctx[BS*SEQ*QKDIM];
__device__ float g_sinv[BS*NH*SEQ];
__device__ float g_probs[(size_t)BS*NH*SEQ*SEQ];   // fallback if probs not in d_out

// ---------------- LayerNorm ----------------
__global__ void ln_kernel(const float* __restrict__ x, const float* __restrict__ gamma,
                          const float* __restrict__ beta, float* __restrict__ xn) {
    int row = blockIdx.x;
    int t = threadIdx.x;
    float v = x[(size_t)row*DM + t];
    float s = v, s2 = v*v;
    #pragma unroll
    for (int o = 16; o; o >>= 1) {
        s  += __shfl_xor_sync(0xffffffffu, s,  o);
        s2 += __shfl_xor_sync(0xffffffffu, s2, o);
    }
    __shared__ float ws[8], ws2[8];
    int w = t >> 5, l = t & 31;
    if (l == 0) { ws[w] = s; ws2[w] = s2; }
    __syncthreads();
    float mean = 0.f, m2 = 0.f;
    #pragma unroll
    for (int i = 0; i < 8; i++) { mean += ws[i]; m2 += ws2[i]; }
    mean *= (1.0f/DM);
    float var = m2*(1.0f/DM) - mean*mean;
    float inv = rsqrtf(var + 1e-5f);
    xn[(size_t)row*DM + t] = (v - mean)*inv*gamma[t] + beta[t];
}

// ================= HMMA NT GEMM mainloop (split-bf16 x3, fp32 acc) =================
#define HG_S 72
#define HG_SMEM (4*128*HG_S*2)   // 73728 B

#define HG_MAINLOOP(ACC)                                                        \
    for (int k0 = 0; k0 < K; k0 += 64) {                                        \
        __syncthreads();                                                        \
        _Pragma("unroll")                                                       \
        for (int c = 0; c < 16; c++) {                                          \
            int idx = c*256 + t;                                                \
            int row = idx >> 5, c2 = (idx & 31)*2;                              \
            float2 v = *(const float2*)&A[(size_t)(bm+row)*K + k0 + c2];        \
            uint32_t hp, lp; split2(v.x, v.y, hp, lp);                          \
            *(uint32_t*)&Ahi[row*HG_S + c2] = hp;                               \
            *(uint32_t*)&Alo[row*HG_S + c2] = lp;                               \
        }                                                                       \
        _Pragma("unroll")                                                       \
        for (int c = 0; c < 16; c++) {                                          \
            int idx = c*256 + t;                                                \
            int row = idx >> 5, c2 = (idx & 31)*2;                              \
            float2 v = *(const float2*)&B[(size_t)(bn+row)*K + k0 + c2];        \
            uint32_t hp, lp; split2(v.x, v.y, hp, lp);                          \
            *(uint32_t*)&Bhi[row*HG_S + c2] = hp;                               \
            *(uint32_t*)&Blo[row*HG_S + c2] = lp;                               \
        }                                                                       \
        __syncthreads();                                                        \
        _Pragma("unroll")                                                       \
        for (int kk = 0; kk < 64; kk += 16) {                                   \
            uint32_t ah[2][4], al[2][4], bh[4][4], bl[4][4];                    \
            ldsm4(ah[0], aAhi + offA0 + kk*2);                                  \
            ldsm4(ah[1], aAhi + offA1 + kk*2);                                  \
            ldsm4(al[0], aAlo + offA0 + kk*2);                                  \
            ldsm4(al[1], aAlo + offA1 + kk*2);                                  \
            _Pragma("unroll")                                                   \
            for (int g = 0; g < 4; g++) {                                       \
                ldsm4(bh[g], aBhi + offB[g] + kk*2);                            \
                ldsm4(bl[g], aBlo + offB[g] + kk*2);                            \
            }                                                                   \
            _Pragma("unroll")                                                   \
            for (int mf = 0; mf < 2; mf++) {                                    \
                _Pragma("unroll")                                               \
                for (int g = 0; g < 4; g++) {                                   \
                    mma_bf16(ACC[mf][2*g+0], ah[mf], bh[g][0], bh[g][2]);       \
                    mma_bf16(ACC[mf][2*g+1], ah[mf], bh[g][1], bh[g][3]);       \
                    mma_bf16(ACC[mf][2*g+0], ah[mf], bl[g][0], bl[g][2]);       \
                    mma_bf16(ACC[mf][2*g+1], ah[mf], bl[g][1], bl[g][3]);       \
                    mma_bf16(ACC[mf][2*g+0], al[mf], bh[g][0], bh[g][2]);       \
                    mma_bf16(ACC[mf][2*g+1], al[mf], bh[g][1], bh[g][3]);       \
                }                                                               \
            }                                                                   \
        }                                                                       \
    }

#define HG_PROLOG                                                               \
    extern __shared__ __nv_bfloat16 smh[];                                      \
    __nv_bfloat16* Ahi = smh;                                                   \
    __nv_bfloat16* Alo = Ahi + 128*HG_S;                                        \
    __nv_bfloat16* Bhi = Alo + 128*HG_S;                                        \
    __nv_bfloat16* Blo = Bhi + 128*HG_S;                                        \
    int t = threadIdx.x, lane = t & 31, w = t >> 5;                             \
    int wm = w & 3, wn = w >> 2;                                                \
    int bm = blockIdx.y*128, bn = blockIdx.x*128;                               \
    uint32_t aAhi = smem_u32(Ahi), aAlo = smem_u32(Alo);                        \
    uint32_t aBhi = smem_u32(Bhi), aBlo = smem_u32(Blo);                        \
    int lrow = lane & 15, lkb = (lane >> 4)*8;                                  \
    uint32_t offA0 = (uint32_t)((wm*32 +  0 + lrow)*HG_S + lkb)*2;              \
    uint32_t offA1 = (uint32_t)((wm*32 + 16 + lrow)*HG_S + lkb)*2;              \
    uint32_t offB[4];                                                           \
    _Pragma("unroll")                                                           \
    for (int g = 0; g < 4; g++)                                                 \
        offB[g] = (uint32_t)((wn*64 + g*16 + lrow)*HG_S + lkb)*2;               \
    float acc[2][8][4];                                                         \
    _Pragma("unroll")                                                           \
    for (int i = 0; i < 2; i++)                                                 \
        _Pragma("unroll")                                                       \
        for (int j = 0; j < 8; j++)                                             \
            _Pragma("unroll")                                                   \
            for (int e = 0; e < 4; e++) acc[i][j][e] = 0.f;

// Q projection: single fp16 plane
__global__ void __launch_bounds__(256, 1) hgemm_q(
        const float* __restrict__ A, const float* __restrict__ B,
        __half* __restrict__ Ch, int M, int Nn, int K) {
    HG_PROLOG
    HG_MAINLOOP(acc)
    int qrow = lane >> 2, qcol = (lane & 3)*2;
    #pragma unroll
    for (int mf = 0; mf < 2; mf++) {
        int m0 = bm + wm*32 + mf*16 + qrow;
        #pragma unroll
        for (int nf = 0; nf < 8; nf++) {
            int nn = bn + wn*64 + nf*8 + qcol;
            *(uint32_t*)&Ch[(size_t)m0*Nn + nn]     = pack_h2(acc[mf][nf][0], acc[mf][nf][1]);
            *(uint32_t*)&Ch[(size_t)(m0+8)*Nn + nn] = pack_h2(acc[mf][nf][2], acc[mf][nf][3]);
        }
    }
}

// K projection: fp16 hi/lo planes
__global__ void __launch_bounds__(256, 1) hgemm_k(
        const float* __restrict__ A, const float* __restrict__ B,
        __half* __restrict__ Chi, __half* __restrict__ Clo,
        int M, int Nn, int K) {
    HG_PROLOG
    HG_MAINLOOP(acc)
    int qrow = lane >> 2, qcol = (lane & 3)*2;
    #pragma unroll
    for (int mf = 0; mf < 2; mf++) {
        int m0 = bm + wm*32 + mf*16 + qrow;
        #pragma unroll
        for (int nf = 0; nf < 8; nf++) {
            int nn = bn + wn*64 + nf*8 + qcol;
            uint32_t h0, l0, h1, l1;
            split2h(acc[mf][nf][0], acc[mf][nf][1], h0, l0);
            split2h(acc[mf][nf][2], acc[mf][nf][3], h1, l1);
            *(uint32_t*)&Chi[(size_t)m0*Nn + nn]     = h0;
            *(uint32_t*)&Clo[(size_t)m0*Nn + nn]     = l0;
            *(uint32_t*)&Chi[(size_t)(m0+8)*Nn + nn] = h1;
            *(uint32_t*)&Clo[(size_t)(m0+8)*Nn + nn] = l1;
        }
    }
}

// output projection: fp32 + residual
__global__ void __launch_bounds__(256, 1) hgemm_res(
        const float* __restrict__ A, const float* __restrict__ B,
        const float* __restrict__ R, float* __restrict__ C,
        int M, int Nn, int K) {
    HG_PROLOG
    HG_MAINLOOP(acc)
    int qrow = lane >> 2, qcol = (lane & 3)*2;
    #pragma unroll
    for (int mf = 0; mf < 2; mf++) {
        int m0 = bm + wm*32 + mf*16 + qrow;
        #pragma unroll
        for (int nf = 0; nf < 8; nf++) {
            int nn = bn + wn*64 + nf*8 + qcol;
            float2 r0 = *(const float2*)&R[(size_t)m0*Nn + nn];
            float2 r1 = *(const float2*)&R[(size_t)(m0+8)*Nn + nn];
            *(float2*)&C[(size_t)m0*Nn + nn]     = make_float2(acc[mf][nf][0]+r0.x, acc[mf][nf][1]+r0.y);
            *(float2*)&C[(size_t)(m0+8)*Nn + nn] = make_float2(acc[mf][nf][2]+r1.x, acc[mf][nf][3]+r1.y);
        }
    }
}

// ================= Scores + exp (fp16 2-pass: Qh·Khi + Qh·Klo) =================
// CTA = (it 128 rows, h, b); 16 warps 4m x 4n; units = (jc in 8) x (kc in 4).
// Writes UNNORMALIZED exp to probs; 1/rowsum to gsinv (ctx normalizes).
#define S6_QS 264
#define S6_KS 72
#define S6_QELEM (128*S6_QS)
#define S6_KELEM (128*S6_KS)
#define S6_SMEM ((S6_QELEM + 4*S6_KELEM)*2 + 2560)   // ~143 KB

__global__ void __launch_bounds__(512, 1) scores_kernel(
        const __half* __restrict__ qh,
        const __half* __restrict__ khi, const __half* __restrict__ klo,
        float* __restrict__ probs, float* __restrict__ gsinv) {
    extern __shared__ __half smsc[];
    __half* sQ = smsc;
    __half* sK = sQ + S6_QELEM;                 // [buf][plane][128*72]
    float* ssum = (float*)(sK + 4*S6_KELEM);    // [128][4]
    int t = threadIdx.x, lane = t & 31, w = t >> 5;
    int wm = w & 3, wn = w >> 2;
    int it = blockIdx.x, hh = blockIdx.y, b = blockIdx.z;

    uint32_t aQ = smem_u32(sQ);
    uint32_t aK = smem_u32(sK);

    // Q plane: 128 rows x 32 16B-chunks (4096 cp.async)
    size_t qgbase = ((size_t)(b*SEQ + it*128))*QKDIM + hh*DM;
    #pragma unroll
    for (int c = 0; c < 8; c++) {
        int idx = c*512 + t;
        int row = idx >> 5, ch = idx & 31;
        cpa16(aQ + (uint32_t)(row*S6_QS + ch*8)*2, qh + qgbase + (size_t)row*QKDIM + ch*8);
    }
    // unit 0
    {
        size_t kb = ((size_t)(b*SEQ))*QKDIM + hh*DM;
        #pragma unroll
        for (int c = 0; c < 4; c++) {
            int idx = c*512 + t;
            int row = idx >> 4, plane = (idx >> 3) & 1, ch = idx & 7;
            const __half* src = (plane ? klo : khi) + kb + (size_t)row*QKDIM + ch*8;
            cpa16(aK + (uint32_t)((plane)*S6_KELEM + row*S6_KS + ch*8)*2, src);
        }
    }
    CP_COMMIT();

    int lrow = lane & 15, lkb = (lane >> 4)*8;
    uint32_t offArow = (uint32_t)((wm*32 + lrow)*S6_QS + lkb)*2;
    uint32_t offBrow = (uint32_t)((wn*32 + lrow)*S6_KS + lkb)*2;
    int qrow = lane >> 2, qcol = (lane & 3)*2;

    float rsum[4] = {0.f, 0.f, 0.f, 0.f};
    float acc[2][4][4];
    size_t pCTA = ((size_t)((b*NH + hh)*SEQ + it*128))*SEQ;

    for (int u = 0; u < 32; u++) {
        int jc = u >> 2, kc = u & 3;
        int buf = u & 1;
        if (u + 1 < 32) {
            int jn = (u+1) >> 2, kn = (u+1) & 3, bn2 = (u+1) & 1;
            size_t kb = ((size_t)(b*SEQ + jn*128))*QKDIM + hh*DM + kn*64;
            #pragma unroll
            for (int c = 0; c < 4; c++) {
                int idx = c*512 + t;
                int row = idx >> 4, plane = (idx >> 3) & 1, ch = idx & 7;
                const __half* src = (plane ? klo : khi) + kb + (size_t)row*QKDIM + ch*8;
                cpa16(aK + (uint32_t)((bn2*2 + plane)*S6_KELEM + row*S6_KS + ch*8)*2, src);
            }
            CP_COMMIT();
            CP_WAIT(1);
        } else {
            CP_WAIT(0);
        }
        __syncthreads();

        if (kc == 0) {
            #pragma unroll
            for (int i = 0; i < 2; i++)
                #pragma unroll
                for (int j = 0; j < 4; j++)
                    #pragma unroll
                    for (int e = 0; e < 4; e++) acc[i][j][e] = 0.f;
        }

        uint32_t aBh = aK + (uint32_t)((buf*2 + 0)*S6_KELEM)*2;
        uint32_t aBl = aK + (uint32_t)((buf*2 + 1)*S6_KELEM)*2;
        uint32_t qk0 = (uint32_t)(kc*64)*2;

        #pragma unroll
        for (int kk = 0; kk < 64; kk += 16) {
            uint32_t Ah[2][4], Bh[2][4], Bl[2][4];
            ldsm4(Ah[0], aQ + offArow + qk0 + kk*2);
            ldsm4(Ah[1], aQ + offArow + (uint32_t)(16*S6_QS)*2 + qk0 + kk*2);
            ldsm4(Bh[0], aBh + offBrow + kk*2);
            ldsm4(Bh[1], aBh + offBrow + (uint32_t)(16*S6_KS)*2 + kk*2);
            ldsm4(Bl[0], aBl + offBrow + kk*2);
            ldsm4(Bl[1], aBl + offBrow + (uint32_t)(16*S6_KS)*2 + kk*2);
            #pragma unroll
            for (int mf = 0; mf < 2; mf++) {
                #pragma unroll
                for (int g = 0; g < 2; g++) {
                    mma_fp16(acc[mf][2*g+0], Ah[mf], Bh[g][0], Bh[g][2]);
                    mma_fp16(acc[mf][2*g+1], Ah[mf], Bh[g][1], Bh[g][3]);
                    mma_fp16(acc[mf][2*g+0], Ah[mf], Bl[g][0], Bl[g][2]);
                    mma_fp16(acc[mf][2*g+1], Ah[mf], Bl[g][1], Bl[g][3]);
                }
            }
        }

        if (kc == 3) {
            // exp (no max-sub; |logit/16| bounded ~±10, fp32-safe), row sums, store
            #pragma unroll
            for (int mf = 0; mf < 2; mf++) {
                size_t ob = pCTA + (size_t)(wm*32 + mf*16 + qrow)*SEQ + jc*128 + wn*32;
                float s0 = 0.f, s1 = 0.f;
                #pragma unroll
                for (int nf = 0; nf < 4; nf++) {
                    float e0 = __expf(acc[mf][nf][0]*0.0625f);
                    float e1 = __expf(acc[mf][nf][1]*0.0625f);
                    float e2 = __expf(acc[mf][nf][2]*0.0625f);
                    float e3 = __expf(acc[mf][nf][3]*0.0625f);
                    s0 += e0 + e1; s1 += e2 + e3;
                    *(float2*)&probs[ob + nf*8 + qcol]                 = make_float2(e0, e1);
                    *(float2*)&probs[ob + (size_t)8*SEQ + nf*8 + qcol] = make_float2(e2, e3);
                }
                rsum[mf*2+0] += s0;
                rsum[mf*2+1] += s1;
            }
        }
        __syncthreads();
    }

    // reduce row sums: 4 lanes per row in-warp, 4 wn-warps via smem; write 1/s
    #pragma unroll
    for (int r = 0; r < 4; r++) {
        rsum[r] += __shfl_xor_sync(0xffffffffu, rsum[r], 1);
        rsum[r] += __shfl_xor_sync(0xffffffffu, rsum[r], 2);
    }
    if ((lane & 3) == 0) {
        #pragma unroll
        for (int mf = 0; mf < 2; mf++)
            #pragma unroll
            for (int hf = 0; hf < 2; hf++)
                ssum[(wm*32 + mf*16 + hf*8 + qrow)*4 + wn] = rsum[mf*2 + hf];
    }
    __syncthreads();
    if (t < 128)
        gsinv[(size_t)(b*NH + hh)*SEQ + it*128 + t] =
            1.0f / (ssum[t*4] + ssum[t*4+1] + ssum[t*4+2] + ssum[t*4+3]);
}

// ================= Context (fp16) + fused probs normalization =================
// CTA = (it, h, b): reads exp-P once, normalizes (×1/s), writes P back, MMA with xn.
#define CX3A_S 136
#define CX3B_S 264
#define CX3_SMEM ((128*CX3A_S + 128*CX3B_S)*2 + 512)   // ~103 KB

__global__ void __launch_bounds__(512, 1) ctx_kernel(
        float* __restrict__ probs, const float* __restrict__ xn,
        const float* __restrict__ gsinv, float* __restrict__ ctx) {
    extern __shared__ __half smcx[];
    __half* As = smcx;                  // [128 i][128 j]
    __half* Bs = As + 128*CX3A_S;       // [128 j][256 d]
    float* ssinv = (float*)(Bs + 128*CX3B_S);   // [128]
    int t = threadIdx.x, lane = t & 31, w = t >> 5;
    int wm = w & 3, wn = w >> 2;
    int it = blockIdx.x, hh = blockIdx.y, b = blockIdx.z;

    if (t < 128) ssinv[t] = gsinv[(size_t)(b*NH + hh)*SEQ + it*128 + t];
    __syncthreads();

    uint32_t aA = smem_u32(As), aB = smem_u32(Bs);
    int lrow = lane & 15, lkb = (lane >> 4)*8;
    uint32_t offA0 = (uint32_t)((wm*32 +  0 + lrow)*CX3A_S + lkb)*2;
    uint32_t offA1 = (uint32_t)((wm*32 + 16 + lrow)*CX3A_S + lkb)*2;
    int trow = (lane & 7) + ((lane >> 3) & 1)*8;
    uint32_t offBt = (uint32_t)(trow*CX3B_S + wn*64 + lkb)*2;

    float acc[2][8][4];
    #pragma unroll
    for (int i = 0; i < 2; i++)
        #pragma unroll
        for (int j = 0; j < 8; j++)
            #pragma unroll
            for (int e = 0; e < 4; e++) acc[i][j][e] = 0.f;

    for (int kc = 0; kc < SEQ/128; kc++) {
        __syncthreads();
        size_t pb = ((size_t)((b*NH + hh)*SEQ + it*128))*SEQ + kc*128;
        #pragma unroll
        for (int c = 0; c < 16; c++) {   // A: P 128x128, normalize + write back + fp16
            int idx = c*512 + t;
            int i = idx >> 6, jp = (idx & 63)*2;
            float iv = ssinv[i];
            float2 v = *(const float2*)&probs[pb + (size_t)i*SEQ + jp];
            v.x *= iv; v.y *= iv;
            *(float2*)&probs[pb + (size_t)i*SEQ + jp] = v;
            *(uint32_t*)&As[i*CX3A_S + jp] = pack_h2(v.x, v.y);
        }
        #pragma unroll
        for (int c = 0; c < 32; c++) {   // B: xn 128x256 f32->fp16
            int idx = c*512 + t;
            int j = idx >> 7, dp = (idx & 127)*2;
            float2 v = *(const float2*)&xn[((size_t)(b*SEQ + kc*128 + j))*DM + dp];
            *(uint32_t*)&Bs[j*CX3B_S + dp] = pack_h2(v.x, v.y);
        }
        __syncthreads();

        #pragma unroll 4
        for (int kk = 0; kk < 128; kk += 16) {
            uint32_t a0[4], a1[4], bb[4][4];
            ldsm4(a0, aA + offA0 + kk*2);
            ldsm4(a1, aA + offA1 + kk*2);
            #pragma unroll
            for (int g = 0; g < 4; g++)
                ldsm4t(bb[g], aB + offBt + (uint32_t)(kk*CX3B_S + g*16)*2);
            #pragma unroll
            for (int g = 0; g < 4; g++) {
                mma_fp16(acc[0][2*g+0], a0, bb[g][0], bb[g][1]);
                mma_fp16(acc[0][2*g+1], a0, bb[g][2], bb[g][3]);
                mma_fp16(acc[1][2*g+0], a1, bb[g][0], bb[g][1]);
                mma_fp16(acc[1][2*g+1], a1, bb[g][2], bb[g][3]);
            }
        }
    }

    int qrow = lane >> 2, qcol = (lane & 3)*2;
    #pragma unroll
    for (int mf = 0; mf < 2; mf++) {
        int i = it*128 + wm*32 + mf*16 + qrow;
        size_t cb = ((size_t)(b*SEQ + i))*QKDIM + hh*DM + wn*64;
        #pragma unroll
        for (int nf = 0; nf < 8; nf++) {
            *(float2*)&ctx[cb + nf*8 + qcol]                   = make_float2(acc[mf][nf][0], acc[mf][nf][1]);
            *(float2*)&ctx[cb + (size_t)8*QKDIM + nf*8 + qcol] = make_float2(acc[mf][nf][2], acc[mf][nf][3]);
        }
    }
}

// ---------------- launch ----------------
extern "C" void kernel_launch(void* const* d_in, const int* in_sizes, int n_in,
                              void* d_out, int out_size) {
    const float* x     = (const float*)d_in[0];
    const float* Wq    = (const float*)d_in[1];
    const float* Wk    = (const float*)d_in[2];
    const float* Wv    = (const float*)d_in[3];
    const float* gamma = (const float*)d_in[4];
    const float* beta  = (const float*)d_in[5];
    float* out = (float*)d_out;

    float *xn, *ctx, *pscr, *sinv;
    __half *qh, *khi, *klo;
    cudaGetSymbolAddress((void**)&xn,   g_xn);
    cudaGetSymbolAddress((void**)&qh,   g_qh);
    cudaGetSymbolAddress((void**)&khi,  g_khi);
    cudaGetSymbolAddress((void**)&klo,  g_klo);
    cudaGetSymbolAddress((void**)&ctx,  g_ctx);
    cudaGetSymbolAddress((void**)&sinv, g_sinv);
    cudaGetSymbolAddress((void**)&pscr, g_probs);

    const long long OUT_ELEMS  = (long long)BS*SEQ*DM;
    const long long PROB_ELEMS = (long long)BS*NH*SEQ*SEQ;
    float* probs = ((long long)out_size >= OUT_ELEMS + PROB_ELEMS) ? (out + OUT_ELEMS) : pscr;

    ln_kernel<<<BS*SEQ, 256>>>(x, gamma, beta, xn);

    cudaFuncSetAttribute(hgemm_q,   cudaFuncAttributeMaxDynamicSharedMemorySize, HG_SMEM);
    cudaFuncSetAttribute(hgemm_k,   cudaFuncAttributeMaxDynamicSharedMemorySize, HG_SMEM);
    cudaFuncSetAttribute(hgemm_res, cudaFuncAttributeMaxDynamicSharedMemorySize, HG_SMEM);
    dim3 gq(QKDIM/128, (BS*SEQ)/128);
    hgemm_q<<<gq, 256, HG_SMEM>>>(xn, Wq, qh, BS*SEQ, QKDIM, DM);
    hgemm_k<<<gq, 256, HG_SMEM>>>(xn, Wk, khi, klo, BS*SEQ, QKDIM, DM);

    cudaFuncSetAttribute(scores_kernel, cudaFuncAttributeMaxDynamicSharedMemorySize, S6_SMEM);
    dim3 gs(SEQ/128, NH, BS);
    scores_kernel<<<gs, 512, S6_SMEM>>>(qh, khi, klo, probs, sinv);

    cudaFuncSetAttribute(ctx_kernel, cudaFuncAttributeMaxDynamicSharedMemorySize, CX3_SMEM);
    dim3 gc(SEQ/128, NH, BS);
    ctx_kernel<<<gc, 512, CX3_SMEM>>>(probs, xn, sinv, ctx);

    dim3 go(DM/128, (BS*SEQ)/128);
    hgemm_res<<<go, 256, HG_SMEM>>>(ctx, Wv, xn, out, BS*SEQ, DM, QKDIM);
}

// round 17
// speedup vs baseline: 1.2607x; 1.2607x over previous
#include <cuda_runtime.h>
#include <cuda_bf16.h>
#include <cuda_fp16.h>
#include <cstdint>

#define BS 16
#define SEQ 1024
#define DM 256
#define NH 8
#define QKDIM (NH*DM)   // 2048

typedef unsigned long long u64;

// ---------------- mma.sync / ldmatrix / cp.async helpers ----------------
__device__ __forceinline__ uint32_t smem_u32(const void* p) {
    uint32_t a;
    asm("{ .reg .u64 t; cvta.to.shared.u64 t, %1; cvt.u32.u64 %0, t; }" : "=r"(a) : "l"(p));
    return a;
}
__device__ __forceinline__ void ldsm4(uint32_t* r, uint32_t addr) {
    asm volatile("ldmatrix.sync.aligned.m8n8.x4.shared.b16 {%0,%1,%2,%3}, [%4];"
        : "=r"(r[0]), "=r"(r[1]), "=r"(r[2]), "=r"(r[3]) : "r"(addr));
}
__device__ __forceinline__ void ldsm4t(uint32_t* r, uint32_t addr) {
    asm volatile("ldmatrix.sync.aligned.m8n8.x4.trans.shared.b16 {%0,%1,%2,%3}, [%4];"
        : "=r"(r[0]), "=r"(r[1]), "=r"(r[2]), "=r"(r[3]) : "r"(addr));
}
__device__ __forceinline__ void mma_fp16(float* c, const uint32_t* a, uint32_t b0, uint32_t b1) {
    asm volatile("mma.sync.aligned.m16n8k16.row.col.f32.f16.f16.f32 "
        "{%0,%1,%2,%3}, {%4,%5,%6,%7}, {%8,%9}, {%0,%1,%2,%3};"
        : "+f"(c[0]), "+f"(c[1]), "+f"(c[2]), "+f"(c[3])
        : "r"(a[0]), "r"(a[1]), "r"(a[2]), "r"(a[3]), "r"(b0), "r"(b1));
}
__device__ __forceinline__ void cpa16(uint32_t saddr, const void* g) {
    asm volatile("cp.async.cg.shared.global [%0], [%1], 16;" :: "r"(saddr), "l"(g));
}
#define CP_COMMIT() asm volatile("cp.async.commit_group;" ::: "memory")
#define CP_WAIT(n)  asm volatile("cp.async.wait_group %0;" :: "n"(n) : "memory")

__device__ __forceinline__ uint32_t pack_h2(float a, float b) {
    __half2 h = __floats2half2_rn(a, b);
    return *reinterpret_cast<uint32_t*>(&h);
}
__device__ __forceinline__ void split2h(float a, float b, uint32_t& hi, uint32_t& lo) {
    __half ha = __float2half_rn(a), hb = __float2half_rn(b);
    __half2 H; H.x = ha; H.y = hb;
    hi = *reinterpret_cast<uint32_t*>(&H);
    lo = pack_h2(a - __half2float(ha), b - __half2float(hb));
}

// ---------------- scratch ----------------
__device__ float g_xn[BS*SEQ*DM];
__device__ __half g_qh[BS*SEQ*QKDIM];
__device__ __half g_kh[BS*SEQ*QKDIM];
__device__ float g_ctx[BS*SEQ*QKDIM];
__device__ float g_sinv[BS*NH*SEQ];
__device__ float g_probs[(size_t)BS*NH*SEQ*SEQ];   // fallback if probs not in d_out

// ---------------- LayerNorm ----------------
__global__ void ln_kernel(const float* __restrict__ x, const float* __restrict__ gamma,
                          const float* __restrict__ beta, float* __restrict__ xn) {
    int row = blockIdx.x;
    int t = threadIdx.x;
    float v = x[(size_t)row*DM + t];
    float s = v, s2 = v*v;
    #pragma unroll
    for (int o = 16; o; o >>= 1) {
        s  += __shfl_xor_sync(0xffffffffu, s,  o);
        s2 += __shfl_xor_sync(0xffffffffu, s2, o);
    }
    __shared__ float ws[8], ws2[8];
    int w = t >> 5, l = t & 31;
    if (l == 0) { ws[w] = s; ws2[w] = s2; }
    __syncthreads();
    float mean = 0.f, m2 = 0.f;
    #pragma unroll
    for (int i = 0; i < 8; i++) { mean += ws[i]; m2 += ws2[i]; }
    mean *= (1.0f/DM);
    float var = m2*(1.0f/DM) - mean*mean;
    float inv = rsqrtf(var + 1e-5f);
    xn[(size_t)row*DM + t] = (v - mean)*inv*gamma[t] + beta[t];
}

// ================= HMMA NT GEMM (fp16 2-pass: Afp16 · (Whi + Wlo)) =================
// C = A @ B^T; 128x128 tile, k-chunk 64; warp tile 32m x 64n; 10 LDSM : 32 MMA.
#define HG_S 72
#define HG_SMEM (3*128*HG_S*2)   // 55296 B

#define HG_PROLOG                                                               \
    extern __shared__ __half smh[];                                             \
    __half* As  = smh;                                                          \
    __half* Bhi = As  + 128*HG_S;                                               \
    __half* Blo = Bhi + 128*HG_S;                                               \
    int t = threadIdx.x, lane = t & 31, w = t >> 5;                             \
    int wm = w & 3, wn = w >> 2;                                                \
    int bm = blockIdx.y*128, bn = blockIdx.x*128;                               \
    uint32_t aAs = smem_u32(As), aBhi = smem_u32(Bhi), aBlo = smem_u32(Blo);    \
    int lrow = lane & 15, lkb = (lane >> 4)*8;                                  \
    uint32_t offA0 = (uint32_t)((wm*32 +  0 + lrow)*HG_S + lkb)*2;              \
    uint32_t offA1 = (uint32_t)((wm*32 + 16 + lrow)*HG_S + lkb)*2;              \
    uint32_t offB[4];                                                           \
    _Pragma("unroll")                                                           \
    for (int g = 0; g < 4; g++)                                                 \
        offB[g] = (uint32_t)((wn*64 + g*16 + lrow)*HG_S + lkb)*2;               \
    float acc[2][8][4];                                                         \
    _Pragma("unroll")                                                           \
    for (int i = 0; i < 2; i++)                                                 \
        _Pragma("unroll")                                                       \
        for (int j = 0; j < 8; j++)                                             \
            _Pragma("unroll")                                                   \
            for (int e = 0; e < 4; e++) acc[i][j][e] = 0.f;

#define HG_MAINLOOP(ACC)                                                        \
    for (int k0 = 0; k0 < K; k0 += 64) {                                        \
        __syncthreads();                                                        \
        _Pragma("unroll")                                                       \
        for (int c = 0; c < 16; c++) {                                          \
            int idx = c*256 + t;                                                \
            int row = idx >> 5, c2 = (idx & 31)*2;                              \
            float2 v = *(const float2*)&A[(size_t)(bm+row)*K + k0 + c2];        \
            *(uint32_t*)&As[row*HG_S + c2] = pack_h2(v.x, v.y);                 \
        }                                                                       \
        _Pragma("unroll")                                                       \
        for (int c = 0; c < 16; c++) {                                          \
            int idx = c*256 + t;                                                \
            int row = idx >> 5, c2 = (idx & 31)*2;                              \
            float2 v = *(const float2*)&B[(size_t)(bn+row)*K + k0 + c2];        \
            uint32_t hp, lp; split2h(v.x, v.y, hp, lp);                         \
            *(uint32_t*)&Bhi[row*HG_S + c2] = hp;                               \
            *(uint32_t*)&Blo[row*HG_S + c2] = lp;                               \
        }                                                                       \
        __syncthreads();                                                        \
        _Pragma("unroll")                                                       \
        for (int kk = 0; kk < 64; kk += 16) {                                   \
            uint32_t ah[2][4], bh[4][4], bl[4][4];                              \
            ldsm4(ah[0], aAs + offA0 + kk*2);                                   \
            ldsm4(ah[1], aAs + offA1 + kk*2);                                   \
            _Pragma("unroll")                                                   \
            for (int g = 0; g < 4; g++) {                                       \
                ldsm4(bh[g], aBhi + offB[g] + kk*2);                            \
                ldsm4(bl[g], aBlo + offB[g] + kk*2);                            \
            }                                                                   \
            _Pragma("unroll")                                                   \
            for (int mf = 0; mf < 2; mf++) {                                    \
                _Pragma("unroll")                                               \
                for (int g = 0; g < 4; g++) {                                   \
                    mma_fp16(ACC[mf][2*g+0], ah[mf], bh[g][0], bh[g][2]);       \
                    mma_fp16(ACC[mf][2*g+1], ah[mf], bh[g][1], bh[g][3]);       \
                    mma_fp16(ACC[mf][2*g+0], ah[mf], bl[g][0], bl[g][2]);       \
                    mma_fp16(ACC[mf][2*g+1], ah[mf], bl[g][1], bl[g][3]);       \
                }                                                               \
            }                                                                   \
        }                                                                       \
    }

// q/k projection: single fp16 output plane
__global__ void __launch_bounds__(256, 1) hgemm_h(
        const float* __restrict__ A, const float* __restrict__ B,
        __half* __restrict__ Ch, int M, int Nn, int K) {
    HG_PROLOG
    HG_MAINLOOP(acc)
    int qrow = lane >> 2, qcol = (lane & 3)*2;
    #pragma unroll
    for (int mf = 0; mf < 2; mf++) {
        int m0 = bm + wm*32 + mf*16 + qrow;
        #pragma unroll
        for (int nf = 0; nf < 8; nf++) {
            int nn = bn + wn*64 + nf*8 + qcol;
            *(uint32_t*)&Ch[(size_t)m0*Nn + nn]     = pack_h2(acc[mf][nf][0], acc[mf][nf][1]);
            *(uint32_t*)&Ch[(size_t)(m0+8)*Nn + nn] = pack_h2(acc[mf][nf][2], acc[mf][nf][3]);
        }
    }
}

// output projection: fp32 + residual
__global__ void __launch_bounds__(256, 1) hgemm_res(
        const float* __restrict__ A, const float* __restrict__ B,
        const float* __restrict__ R, float* __restrict__ C,
        int M, int Nn, int K) {
    HG_PROLOG
    HG_MAINLOOP(acc)
    int qrow = lane >> 2, qcol = (lane & 3)*2;
    #pragma unroll
    for (int mf = 0; mf < 2; mf++) {
        int m0 = bm + wm*32 + mf*16 + qrow;
        #pragma unroll
        for (int nf = 0; nf < 8; nf++) {
            int nn = bn + wn*64 + nf*8 + qcol;
            float2 r0 = *(const float2*)&R[(size_t)m0*Nn + nn];
            float2 r1 = *(const float2*)&R[(size_t)(m0+8)*Nn + nn];
            *(float2*)&C[(size_t)m0*Nn + nn]     = make_float2(acc[mf][nf][0]+r0.x, acc[mf][nf][1]+r0.y);
            *(float2*)&C[(size_t)(m0+8)*Nn + nn] = make_float2(acc[mf][nf][2]+r1.x, acc[mf][nf][3]+r1.y);
        }
    }
}

// ================= Scores + exp (fp16 single pass: Qh·Kh) =================
// CTA = (it 128 rows, h, b); 16 warps 4m x 4n; units = (jc in 8) x (kc in 4).
// Writes UNNORMALIZED exp to probs; 1/rowsum to gsinv (ctx normalizes).
#define S7_QS 264
#define S7_KS 72
#define S7_QELEM (128*S7_QS)
#define S7_KELEM (128*S7_KS)
#define S7_SMEM ((S7_QELEM + 2*S7_KELEM)*2 + 2560)   // ~107 KB

__global__ void __launch_bounds__(512, 1) scores_kernel(
        const __half* __restrict__ qh, const __half* __restrict__ kh,
        float* __restrict__ probs, float* __restrict__ gsinv) {
    extern __shared__ __half smsc[];
    __half* sQ = smsc;
    __half* sK = sQ + S7_QELEM;                 // [buf][128*72]
    float* ssum = (float*)(sK + 2*S7_KELEM);    // [128][4]
    int t = threadIdx.x, lane = t & 31, w = t >> 5;
    int wm = w & 3, wn = w >> 2;
    int it = blockIdx.x, hh = blockIdx.y, b = blockIdx.z;

    uint32_t aQ = smem_u32(sQ);
    uint32_t aK = smem_u32(sK);

    // Q plane: 128 rows x 32 16B-chunks
    size_t qgbase = ((size_t)(b*SEQ + it*128))*QKDIM + hh*DM;
    #pragma unroll
    for (int c = 0; c < 8; c++) {
        int idx = c*512 + t;
        int row = idx >> 5, ch = idx & 31;
        cpa16(aQ + (uint32_t)(row*S7_QS + ch*8)*2, qh + qgbase + (size_t)row*QKDIM + ch*8);
    }
    // unit 0: 128 rows x 64 k (1024 chunks)
    {
        size_t kb = ((size_t)(b*SEQ))*QKDIM + hh*DM;
        #pragma unroll
        for (int c = 0; c < 2; c++) {
            int idx = c*512 + t;
            int row = idx >> 3, ch = idx & 7;
            cpa16(aK + (uint32_t)(row*S7_KS + ch*8)*2, kh + kb + (size_t)row*QKDIM + ch*8);
        }
    }
    CP_COMMIT();

    int lrow = lane & 15, lkb = (lane >> 4)*8;
    uint32_t offArow = (uint32_t)((wm*32 + lrow)*S7_QS + lkb)*2;
    uint32_t offBrow = (uint32_t)((wn*32 + lrow)*S7_KS + lkb)*2;
    int qrow = lane >> 2, qcol = (lane & 3)*2;

    float rsum[4] = {0.f, 0.f, 0.f, 0.f};
    float acc[2][4][4];
    size_t pCTA = ((size_t)((b*NH + hh)*SEQ + it*128))*SEQ;

    for (int u = 0; u < 32; u++) {
        int jc = u >> 2, kc = u & 3;
        int buf = u & 1;
        if (u + 1 < 32) {
            int jn = (u+1) >> 2, kn = (u+1) & 3, bn2 = (u+1) & 1;
            size_t kb = ((size_t)(b*SEQ + jn*128))*QKDIM + hh*DM + kn*64;
            #pragma unroll
            for (int c = 0; c < 2; c++) {
                int idx = c*512 + t;
                int row = idx >> 3, ch = idx & 7;
                cpa16(aK + (uint32_t)(bn2*S7_KELEM + row*S7_KS + ch*8)*2,
                      kh + kb + (size_t)row*QKDIM + ch*8);
            }
            CP_COMMIT();
            CP_WAIT(1);
        } else {
            CP_WAIT(0);
        }
        __syncthreads();

        if (kc == 0) {
            #pragma unroll
            for (int i = 0; i < 2; i++)
                #pragma unroll
                for (int j = 0; j < 4; j++)
                    #pragma unroll
                    for (int e = 0; e < 4; e++) acc[i][j][e] = 0.f;
        }

        uint32_t aB = aK + (uint32_t)(buf*S7_KELEM)*2;
        uint32_t qk0 = (uint32_t)(kc*64)*2;

        #pragma unroll
        for (int kk = 0; kk < 64; kk += 16) {
            uint32_t Ah[2][4], Bh[2][4];
            ldsm4(Ah[0], aQ + offArow + qk0 + kk*2);
            ldsm4(Ah[1], aQ + offArow + (uint32_t)(16*S7_QS)*2 + qk0 + kk*2);
            ldsm4(Bh[0], aB + offBrow + kk*2);
            ldsm4(Bh[1], aB + offBrow + (uint32_t)(16*S7_KS)*2 + kk*2);
            #pragma unroll
            for (int mf = 0; mf < 2; mf++) {
                #pragma unroll
                for (int g = 0; g < 2; g++) {
                    mma_fp16(acc[mf][2*g+0], Ah[mf], Bh[g][0], Bh[g][2]);
                    mma_fp16(acc[mf][2*g+1], Ah[mf], Bh[g][1], Bh[g][3]);
                }
            }
        }

        if (kc == 3) {
            // exp (no max-sub; |logit/16| bounded ~±10, fp32-safe), row sums, store
            #pragma unroll
            for (int mf = 0; mf < 2; mf++) {
                size_t ob = pCTA + (size_t)(wm*32 + mf*16 + qrow)*SEQ + jc*128 + wn*32;
                float s0 = 0.f, s1 = 0.f;
                #pragma unroll
                for (int nf = 0; nf < 4; nf++) {
                    float e0 = __expf(acc[mf][nf][0]*0.0625f);
                    float e1 = __expf(acc[mf][nf][1]*0.0625f);
                    float e2 = __expf(acc[mf][nf][2]*0.0625f);
                    float e3 = __expf(acc[mf][nf][3]*0.0625f);
                    s0 += e0 + e1; s1 += e2 + e3;
                    *(float2*)&probs[ob + nf*8 + qcol]                 = make_float2(e0, e1);
                    *(float2*)&probs[ob + (size_t)8*SEQ + nf*8 + qcol] = make_float2(e2, e3);
                }
                rsum[mf*2+0] += s0;
                rsum[mf*2+1] += s1;
            }
        }
        __syncthreads();
    }

    // reduce row sums: 4 lanes per row in-warp, 4 wn-warps via smem; write 1/s
    #pragma unroll
    for (int r = 0; r < 4; r++) {
        rsum[r] += __shfl_xor_sync(0xffffffffu, rsum[r], 1);
        rsum[r] += __shfl_xor_sync(0xffffffffu, rsum[r], 2);
    }
    if ((lane & 3) == 0) {
        #pragma unroll
        for (int mf = 0; mf < 2; mf++)
            #pragma unroll
            for (int hf = 0; hf < 2; hf++)
                ssum[(wm*32 + mf*16 + hf*8 + qrow)*4 + wn] = rsum[mf*2 + hf];
    }
    __syncthreads();
    if (t < 128)
        gsinv[(size_t)(b*NH + hh)*SEQ + it*128 + t] =
            1.0f / (ssum[t*4] + ssum[t*4+1] + ssum[t*4+2] + ssum[t*4+3]);
}

// ================= Context (fp16) + fused probs normalization =================
#define CX3A_S 136
#define CX3B_S 264
#define CX3_SMEM ((128*CX3A_S + 128*CX3B_S)*2 + 512)   // ~103 KB

__global__ void __launch_bounds__(512, 1) ctx_kernel(
        float* __restrict__ probs, const float* __restrict__ xn,
        const float* __restrict__ gsinv, float* __restrict__ ctx) {
    extern __shared__ __half smcx[];
    __half* As = smcx;                  // [128 i][128 j]
    __half* Bs = As + 128*CX3A_S;       // [128 j][256 d]
    float* ssinv = (float*)(Bs + 128*CX3B_S);   // [128]
    int t = threadIdx.x, lane = t & 31, w = t >> 5;
    int wm = w & 3, wn = w >> 2;
    int it = blockIdx.x, hh = blockIdx.y, b = blockIdx.z;

    if (t < 128) ssinv[t] = gsinv[(size_t)(b*NH + hh)*SEQ + it*128 + t];
    __syncthreads();

    uint32_t aA = smem_u32(As), aB = smem_u32(Bs);
    int lrow = lane & 15, lkb = (lane >> 4)*8;
    uint32_t offA0 = (uint32_t)((wm*32 +  0 + lrow)*CX3A_S + lkb)*2;
    uint32_t offA1 = (uint32_t)((wm*32 + 16 + lrow)*CX3A_S + lkb)*2;
    int trow = (lane & 7) + ((lane >> 3) & 1)*8;
    uint32_t offBt = (uint32_t)(trow*CX3B_S + wn*64 + lkb)*2;

    float acc[2][8][4];
    #pragma unroll
    for (int i = 0; i < 2; i++)
        #pragma unroll
        for (int j = 0; j < 8; j++)
            #pragma unroll
            for (int e = 0; e < 4; e++) acc[i][j][e] = 0.f;

    for (int kc = 0; kc < SEQ/128; kc++) {
        __syncthreads();
        size_t pb = ((size_t)((b*NH + hh)*SEQ + it*128))*SEQ + kc*128;
        #pragma unroll
        for (int c = 0; c < 16; c++) {   // A: P 128x128, normalize + write back + fp16
            int idx = c*512 + t;
            int i = idx >> 6, jp = (idx & 63)*2;
            float iv = ssinv[i];
            float2 v = *(const float2*)&probs[pb + (size_t)i*SEQ + jp];
            v.x *= iv; v.y *= iv;
            *(float2*)&probs[pb + (size_t)i*SEQ + jp] = v;
            *(uint32_t*)&As[i*CX3A_S + jp] = pack_h2(v.x, v.y);
        }
        #pragma unroll
        for (int c = 0; c < 32; c++) {   // B: xn 128x256 f32->fp16
            int idx = c*512 + t;
            int j = idx >> 7, dp = (idx & 127)*2;
            float2 v = *(const float2*)&xn[((size_t)(b*SEQ + kc*128 + j))*DM + dp];
            *(uint32_t*)&Bs[j*CX3B_S + dp] = pack_h2(v.x, v.y);
        }
        __syncthreads();

        #pragma unroll 4
        for (int kk = 0; kk < 128; kk += 16) {
            uint32_t a0[4], a1[4], bb[4][4];
            ldsm4(a0, aA + offA0 + kk*2);
            ldsm4(a1, aA + offA1 + kk*2);
            #pragma unroll
            for (int g = 0; g < 4; g++)
                ldsm4t(bb[g], aB + offBt + (uint32_t)(kk*CX3B_S + g*16)*2);
            #pragma unroll
            for (int g = 0; g < 4; g++) {
                mma_fp16(acc[0][2*g+0], a0, bb[g][0], bb[g][1]);
                mma_fp16(acc[0][2*g+1], a0, bb[g][2], bb[g][3]);
                mma_fp16(acc[1][2*g+0], a1, bb[g][0], bb[g][1]);
                mma_fp16(acc[1][2*g+1], a1, bb[g][2], bb[g][3]);
            }
        }
    }

    int qrow = lane >> 2, qcol = (lane & 3)*2;
    #pragma unroll
    for (int mf = 0; mf < 2; mf++) {
        int i = it*128 + wm*32 + mf*16 + qrow;
        size_t cb = ((size_t)(b*SEQ + i))*QKDIM + hh*DM + wn*64;
        #pragma unroll
        for (int nf = 0; nf < 8; nf++) {
            *(float2*)&ctx[cb + nf*8 + qcol]                   = make_float2(acc[mf][nf][0], acc[mf][nf][1]);
            *(float2*)&ctx[cb + (size_t)8*QKDIM + nf*8 + qcol] = make_float2(acc[mf][nf][2], acc[mf][nf][3]);
        }
    }
}

// ---------------- launch ----------------
extern "C" void kernel_launch(void* const* d_in, const int* in_sizes, int n_in,
                              void* d_out, int out_size) {
    const float* x     = (const float*)d_in[0];
    const float* Wq    = (const float*)d_in[1];
    const float* Wk    = (const float*)d_in[2];
    const float* Wv    = (const float*)d_in[3];
    const float* gamma = (const float*)d_in[4];
    const float* beta  = (const float*)d_in[5];
    float* out = (float*)d_out;

    float *xn, *ctx, *pscr, *sinv;
    __half *qh, *kh;
    cudaGetSymbolAddress((void**)&xn,   g_xn);
    cudaGetSymbolAddress((void**)&qh,   g_qh);
    cudaGetSymbolAddress((void**)&kh,   g_kh);
    cudaGetSymbolAddress((void**)&ctx,  g_ctx);
    cudaGetSymbolAddress((void**)&sinv, g_sinv);
    cudaGetSymbolAddress((void**)&pscr, g_probs);

    const long long OUT_ELEMS  = (long long)BS*SEQ*DM;
    const long long PROB_ELEMS = (long long)BS*NH*SEQ*SEQ;
    float* probs = ((long long)out_size >= OUT_ELEMS + PROB_ELEMS) ? (out + OUT_ELEMS) : pscr;

    ln_kernel<<<BS*SEQ, 256>>>(x, gamma, beta, xn);

    cudaFuncSetAttribute(hgemm_h,   cudaFuncAttributeMaxDynamicSharedMemorySize, HG_SMEM);
    cudaFuncSetAttribute(hgemm_res, cudaFuncAttributeMaxDynamicSharedMemorySize, HG_SMEM);
    dim3 gq(QKDIM/128, (BS*SEQ)/128);
    hgemm_h<<<gq, 256, HG_SMEM>>>(xn, Wq, qh, BS*SEQ, QKDIM, DM);
    hgemm_h<<<gq, 256, HG_SMEM>>>(xn, Wk, kh, BS*SEQ, QKDIM, DM);

    cudaFuncSetAttribute(scores_kernel, cudaFuncAttributeMaxDynamicSharedMemorySize, S7_SMEM);
    dim3 gs(SEQ/128, NH, BS);
    scores_kernel<<<gs, 512, S7_SMEM>>>(qh, kh, probs, sinv);

    cudaFuncSetAttribute(ctx_kernel, cudaFuncAttributeMaxDynamicSharedMemorySize, CX3_SMEM);
    dim3 gc(SEQ/128, NH, BS);
    ctx_kernel<<<gc, 512, CX3_SMEM>>>(probs, xn, sinv, ctx);

    dim3 go(DM/128, (BS*SEQ)/128);
    hgemm_res<<<go, 256, HG_SMEM>>>(ctx, Wv, xn, out, BS*SEQ, DM, QKDIM);
}